// round 1
// baseline (speedup 1.0000x reference)
#include <cuda_runtime.h>
#include <math.h>

#define B_   256
#define T_   256
#define D_   512
#define H_   512
#define O_   256
#define EPS_ 1e-5f

#define G_   128   // persistent CTAs (< 148 SMs -> all co-resident, barrier is safe)
#define HC_  4     // feature columns per CTA (G_*HC_ == H_)
#define NT_  256   // threads per CTA (one batch row per thread)

// ---------------- static device scratch (no allocations allowed) ----------------
__device__ float d_xT[(size_t)T_ * D_ * B_];   // x transposed: [t][k][i]
__device__ float d_h0 [H_ * B_];               // layer-0 state   [j][i]
__device__ float d_hm0[H_ * B_];               // middle state 0  [j][i]
__device__ float d_hm1[H_ * B_];               // middle state 1  [j][i]

__device__ unsigned          g_cnt;            // barrier arrive counter
__device__ volatile unsigned g_gen;            // barrier generation

// ---------------- software grid barrier (all CTAs resident) ----------------
__device__ __forceinline__ void gsync() {
    __syncthreads();
    if (threadIdx.x == 0) {
        __threadfence();                       // release my writes to L2
        unsigned my = g_gen;
        if (atomicAdd(&g_cnt, 1u) == (unsigned)(G_ - 1)) {
            g_cnt = 0u;
            __threadfence();
            g_gen = my + 1u;
        } else {
            while (g_gen == my) { __nanosleep(64); }
            __threadfence();                   // acquire
        }
    }
    __syncthreads();
}

// ---------------- block reductions ----------------
// Reduce 8 values (sum) across 256 threads; results broadcast via sfin[0..7].
__device__ __forceinline__ void block_reduce8(float v[8], float* sred /*64*/, float* sfin /*8*/) {
    __syncthreads();                           // protect smem reuse
    #pragma unroll
    for (int off = 16; off > 0; off >>= 1) {
        #pragma unroll
        for (int q = 0; q < 8; q++) v[q] += __shfl_down_sync(0xffffffffu, v[q], off);
    }
    int w = threadIdx.x >> 5;
    if ((threadIdx.x & 31) == 0) {
        #pragma unroll
        for (int q = 0; q < 8; q++) sred[q * 8 + w] = v[q];
    }
    __syncthreads();
    if (threadIdx.x < 8) {
        float s = 0.f;
        #pragma unroll
        for (int ww = 0; ww < 8; ww++) s += sred[threadIdx.x * 8 + ww];
        sfin[threadIdx.x] = s;
    }
    __syncthreads();
}

__device__ __forceinline__ float block_allreduce_max(float v, float* s8) {
    __syncthreads();
    #pragma unroll
    for (int off = 16; off > 0; off >>= 1)
        v = fmaxf(v, __shfl_xor_sync(0xffffffffu, v, off));
    if ((threadIdx.x & 31) == 0) s8[threadIdx.x >> 5] = v;
    __syncthreads();
    float m = s8[0];
    #pragma unroll
    for (int w = 1; w < 8; w++) m = fmaxf(m, s8[w]);
    return m;
}

__device__ __forceinline__ float block_allreduce_sum(float v, float* s8) {
    __syncthreads();
    #pragma unroll
    for (int off = 16; off > 0; off >>= 1)
        v += __shfl_xor_sync(0xffffffffu, v, off);
    if ((threadIdx.x & 31) == 0) s8[threadIdx.x >> 5] = v;
    __syncthreads();
    float s = 0.f;
    #pragma unroll
    for (int w = 0; w < 8; w++) s += s8[w];
    return s;
}

// ---------------- one IndRNN cell for this CTA's HC_ columns ----------------
// in : [512][B_] activation (gmem, other CTAs wrote it -> .cg loads)
// hst: &state[jbase*B_]  (this CTA's rows of the layer state; read old, write new)
// Wsm: smem [HC_][512] weight rows;  prm: smem [6][HC_] = b,u,g1,be1,g2,be2
__device__ __forceinline__ void run_cell(const float* __restrict__ in,
                                         float* __restrict__ hst,
                                         const float* __restrict__ Wsm,
                                         const float* __restrict__ prm,
                                         float* sred, float* sfin) {
    const int i = threadIdx.x;
    float acc0[HC_], acc1[HC_];
    #pragma unroll
    for (int c = 0; c < HC_; c++) { acc0[c] = 0.f; acc1[c] = 0.f; }

    const float* inp = in + i;
    #pragma unroll 2
    for (int k = 0; k < 512; k += 8) {
        float a0 = __ldcg(inp + (size_t)(k + 0) * B_);
        float a1 = __ldcg(inp + (size_t)(k + 1) * B_);
        float a2 = __ldcg(inp + (size_t)(k + 2) * B_);
        float a3 = __ldcg(inp + (size_t)(k + 3) * B_);
        float a4 = __ldcg(inp + (size_t)(k + 4) * B_);
        float a5 = __ldcg(inp + (size_t)(k + 5) * B_);
        float a6 = __ldcg(inp + (size_t)(k + 6) * B_);
        float a7 = __ldcg(inp + (size_t)(k + 7) * B_);
        #pragma unroll
        for (int c = 0; c < HC_; c++) {
            const float4* wp = (const float4*)(Wsm + c * 512 + k);
            float4 wA = wp[0];
            float4 wB = wp[1];
            acc0[c] = fmaf(a0, wA.x, acc0[c]);
            acc1[c] = fmaf(a1, wA.y, acc1[c]);
            acc0[c] = fmaf(a2, wA.z, acc0[c]);
            acc1[c] = fmaf(a3, wA.w, acc1[c]);
            acc0[c] = fmaf(a4, wB.x, acc0[c]);
            acc1[c] = fmaf(a5, wB.y, acc1[c]);
            acc0[c] = fmaf(a6, wB.z, acc0[c]);
            acc1[c] = fmaf(a7, wB.w, acc1[c]);
        }
    }

    float z[HC_];
    #pragma unroll
    for (int c = 0; c < HC_; c++) z[c] = acc0[c] + acc1[c] + prm[0 * HC_ + c];

    // BN1 stats (sum, sumsq per column)
    float v8[8];
    #pragma unroll
    for (int c = 0; c < HC_; c++) { v8[2 * c] = z[c]; v8[2 * c + 1] = z[c] * z[c]; }
    block_reduce8(v8, sred, sfin);

    #pragma unroll
    for (int c = 0; c < HC_; c++) {
        float m   = sfin[2 * c] * (1.f / B_);
        float var = sfin[2 * c + 1] * (1.f / B_) - m * m;
        float rs  = rsqrtf(var + EPS_);
        float o1  = (z[c] - m) * rs * prm[2 * HC_ + c] + prm[3 * HC_ + c];
        float hv  = __ldcg(hst + c * B_ + i);
        z[c] = fmaxf(fmaf(hv, prm[1 * HC_ + c], o1), 0.f);   // relu(o1 + h*u)
    }

    // BN2 stats
    #pragma unroll
    for (int c = 0; c < HC_; c++) { v8[2 * c] = z[c]; v8[2 * c + 1] = z[c] * z[c]; }
    block_reduce8(v8, sred, sfin);

    #pragma unroll
    for (int c = 0; c < HC_; c++) {
        float m   = sfin[2 * c] * (1.f / B_);
        float var = sfin[2 * c + 1] * (1.f / B_) - m * m;
        float rs  = rsqrtf(var + EPS_);
        float o   = (z[c] - m) * rs * prm[4 * HC_ + c] + prm[5 * HC_ + c];
        __stcg(hst + c * B_ + i, o);                          // new state = layer output
    }
}

// ---------------- transpose x: [B][T][D] -> [T][D][B] ----------------
__global__ void transpose_kernel(const float* __restrict__ x) {
    __shared__ float sm[32][33];
    int t  = blockIdx.x;
    int k0 = blockIdx.y * 32;
    int i0 = blockIdx.z * 32;
    int tx = threadIdx.x, ty = threadIdx.y;
    sm[ty][tx] = x[((size_t)(i0 + ty) * T_ + t) * D_ + (k0 + tx)];
    __syncthreads();
    d_xT[((size_t)t * D_ + (k0 + ty)) * B_ + (i0 + tx)] = sm[tx][ty];
}

// ---------------- persistent recurrent kernel ----------------
__global__ void __launch_bounds__(NT_, 1) rnn_kernel(
    const float* __restrict__ W0,  const float* __restrict__ b0,
    const float* __restrict__ u0,  const float* __restrict__ g10,
    const float* __restrict__ be10,const float* __restrict__ g20,
    const float* __restrict__ be20,
    const float* __restrict__ Wm,  const float* __restrict__ bm,
    const float* __restrict__ um,  const float* __restrict__ g1m,
    const float* __restrict__ be1m,const float* __restrict__ g2m,
    const float* __restrict__ be2m,
    const float* __restrict__ Wfc, const float* __restrict__ bfc,
    float* __restrict__ out) {

    __shared__ __align__(16) float W0s[HC_ * 512];
    __shared__ __align__(16) float Wms[HC_ * 512];
    __shared__ float p0[6 * HC_], pm[6 * HC_];
    __shared__ float sred[64], sfin[8];
    __shared__ float hrow[H_];

    const int tid   = threadIdx.x;
    const int jbase = blockIdx.x * HC_;

    // Stage this CTA's weight rows + per-column params into smem.
    for (int idx = tid; idx < HC_ * 512; idx += NT_) {
        int c = idx >> 9, k = idx & 511;
        W0s[idx] = W0[(size_t)(jbase + c) * D_ + k];
        Wms[idx] = Wm[(size_t)(jbase + c) * H_ + k];
    }
    if (tid < HC_) {
        int j = jbase + tid;
        p0[0 * HC_ + tid] = b0[j];  p0[1 * HC_ + tid] = u0[j];
        p0[2 * HC_ + tid] = g10[j]; p0[3 * HC_ + tid] = be10[j];
        p0[4 * HC_ + tid] = g20[j]; p0[5 * HC_ + tid] = be20[j];
        pm[0 * HC_ + tid] = bm[j];  pm[1 * HC_ + tid] = um[j];
        pm[2 * HC_ + tid] = g1m[j]; pm[3 * HC_ + tid] = be1m[j];
        pm[4 * HC_ + tid] = g2m[j]; pm[5 * HC_ + tid] = be2m[j];
    }
    // Zero this CTA's state slices (must be per-launch: harness replays the graph).
    #pragma unroll
    for (int c = 0; c < HC_; c++) {
        __stcg(&d_h0 [(size_t)(jbase + c) * B_ + tid], 0.f);
        __stcg(&d_hm0[(size_t)(jbase + c) * B_ + tid], 0.f);
        __stcg(&d_hm1[(size_t)(jbase + c) * B_ + tid], 0.f);
    }
    __syncthreads();
    gsync();

    // ---- sequential scan: 2 grid syncs per timestep ----
    for (int t = 0; t < T_; t++) {
        run_cell(d_xT + (size_t)t * D_ * B_, d_h0 + (size_t)jbase * B_, W0s, p0, sred, sfin);
        gsync();   // all of h0(t) visible before L1 reads it
        run_cell(d_h0,  d_hm0 + (size_t)jbase * B_, Wms, pm, sred, sfin);
        gsync();   // all of hm0(t) visible before L2 reads it; also fences h0 reads
        run_cell(d_hm0, d_hm1 + (size_t)jbase * B_, Wms, pm, sred, sfin);
        // no sync needed: next L0 touches only xT + its own h0 columns;
        // hm0 is not rewritten until after the next gsync.
    }
    gsync();       // hm1 final visible to everyone for the head

    // ---- head: logits = hm1 @ Wfc^T + bfc, then log_softmax over O ----
    // Each CTA handles 2 batch rows; thread tid = output class o.
    for (int rr = 0; rr < 2; rr++) {
        int r = blockIdx.x * 2 + rr;
        __syncthreads();
        for (int j = tid; j < H_; j += NT_) hrow[j] = __ldcg(&d_hm1[(size_t)j * B_ + r]);
        __syncthreads();

        float acc = bfc[tid];
        const float4* wrow = (const float4*)(Wfc + (size_t)tid * H_);
        #pragma unroll 4
        for (int j4 = 0; j4 < H_ / 4; j4++) {
            float4 w = wrow[j4];
            acc = fmaf(hrow[4 * j4 + 0], w.x, acc);
            acc = fmaf(hrow[4 * j4 + 1], w.y, acc);
            acc = fmaf(hrow[4 * j4 + 2], w.z, acc);
            acc = fmaf(hrow[4 * j4 + 3], w.w, acc);
        }
        float mx = block_allreduce_max(acc, sfin);
        float se = block_allreduce_sum(expf(acc - mx), sfin);
        out[(size_t)r * O_ + tid] = acc - mx - logf(se);
    }
}

// ---------------- harness entry ----------------
extern "C" void kernel_launch(void* const* d_in, const int* in_sizes, int n_in,
                              void* d_out, int out_size) {
    (void)in_sizes; (void)n_in; (void)out_size;
    const float* x    = (const float*)d_in[0];
    const float* W0   = (const float*)d_in[1];
    const float* b0   = (const float*)d_in[2];
    const float* u0   = (const float*)d_in[3];
    const float* g10  = (const float*)d_in[4];
    const float* be10 = (const float*)d_in[5];
    const float* g20  = (const float*)d_in[6];
    const float* be20 = (const float*)d_in[7];
    const float* Wm   = (const float*)d_in[8];
    const float* bm   = (const float*)d_in[9];
    const float* um   = (const float*)d_in[10];
    const float* g1m  = (const float*)d_in[11];
    const float* be1m = (const float*)d_in[12];
    const float* g2m  = (const float*)d_in[13];
    const float* be2m = (const float*)d_in[14];
    const float* Wfc  = (const float*)d_in[15];
    const float* bfc  = (const float*)d_in[16];
    float* out = (float*)d_out;

    transpose_kernel<<<dim3(T_, D_ / 32, B_ / 32), dim3(32, 32)>>>(x);
    rnn_kernel<<<G_, NT_>>>(W0, b0, u0, g10, be10, g20, be20,
                            Wm, bm, um, g1m, be1m, g2m, be2m,
                            Wfc, bfc, out);
}

// round 2
// speedup vs baseline: 1.5629x; 1.5629x over previous
#include <cuda_runtime.h>
#include <math.h>

#define B_   256
#define T_   256
#define D_   512
#define H_   512
#define O_   256
#define EPS_ 1e-5f

#define G_   128   // persistent CTAs (< 148 SMs -> all co-resident)
#define HC_  4     // feature columns per CTA (G_*HC_ == H_)
#define NT_  512   // 128 batch-pairs x 4 k-groups
#define NG_  4     // k-groups
#define KG_  128   // k per group (NG_*KG_ == 512)
#define NW_  (NT_/32)

// ---------------- static device scratch ----------------
__device__ float d_xT[(size_t)T_ * D_ * B_];   // x transposed: [t][k][i]
__device__ float d_h0 [H_ * B_];
__device__ float d_hm0[H_ * B_];
__device__ float d_hm1[H_ * B_];

__device__ unsigned          g_cnt;
__device__ volatile unsigned g_gen;

// ---------------- packed f32x2 helpers ----------------
__device__ __forceinline__ unsigned long long pk2(float x, float y) {
    unsigned long long r;
    asm("mov.b64 %0, {%1, %2};" : "=l"(r) : "f"(x), "f"(y));
    return r;
}
__device__ __forceinline__ void upk2(float& x, float& y, unsigned long long v) {
    asm("mov.b64 {%0, %1}, %2;" : "=f"(x), "=f"(y) : "l"(v));
}
__device__ __forceinline__ void fma2(unsigned long long& d, unsigned long long a,
                                     unsigned long long b) {
    asm("fma.rn.f32x2 %0, %1, %2, %0;" : "+l"(d) : "l"(a), "l"(b));
}

// ---------------- software grid barrier ----------------
__device__ __forceinline__ void gsync() {
    __syncthreads();
    if (threadIdx.x == 0) {
        __threadfence();
        unsigned my = g_gen;
        if (atomicAdd(&g_cnt, 1u) == (unsigned)(G_ - 1)) {
            g_cnt = 0u;
            __threadfence();
            g_gen = my + 1u;
        } else {
            while (g_gen == my) { __nanosleep(64); }
            __threadfence();
        }
    }
    __syncthreads();
}

// ---------------- block reductions (16 warps) ----------------
__device__ __forceinline__ void block_reduce8(float v[8], float* sred /*8*16*/,
                                              float* sfin /*8*/) {
    __syncthreads();
    #pragma unroll
    for (int off = 16; off > 0; off >>= 1) {
        #pragma unroll
        for (int q = 0; q < 8; q++) v[q] += __shfl_down_sync(0xffffffffu, v[q], off);
    }
    int w = threadIdx.x >> 5;
    if ((threadIdx.x & 31) == 0) {
        #pragma unroll
        for (int q = 0; q < 8; q++) sred[q * NW_ + w] = v[q];
    }
    __syncthreads();
    if (threadIdx.x < 8) {
        float s = 0.f;
        #pragma unroll
        for (int ww = 0; ww < NW_; ww++) s += sred[threadIdx.x * NW_ + ww];
        sfin[threadIdx.x] = s;
    }
    __syncthreads();
}

__device__ __forceinline__ float block_allreduce_max(float v, float* s) {
    __syncthreads();
    #pragma unroll
    for (int off = 16; off > 0; off >>= 1)
        v = fmaxf(v, __shfl_xor_sync(0xffffffffu, v, off));
    if ((threadIdx.x & 31) == 0) s[threadIdx.x >> 5] = v;
    __syncthreads();
    float m = s[0];
    #pragma unroll
    for (int w = 1; w < NW_; w++) m = fmaxf(m, s[w]);
    return m;
}

__device__ __forceinline__ float block_allreduce_sum(float v, float* s) {
    __syncthreads();
    #pragma unroll
    for (int off = 16; off > 0; off >>= 1)
        v += __shfl_xor_sync(0xffffffffu, v, off);
    if ((threadIdx.x & 31) == 0) s[threadIdx.x >> 5] = v;
    __syncthreads();
    float r = 0.f;
    #pragma unroll
    for (int w = 0; w < NW_; w++) r += s[w];
    return r;
}

// ---------------- one IndRNN cell ----------------
// in : [512][B_] activation in gmem (L2-coherent via .cg)
// hst: &state[jbase*B_] (this CTA's HC_ rows)
// Wd : smem, HC_*512 packed-duplicated weights (w,w)
// prm: smem [6][HC_] = b,u,g1,be1,g2,be2
// pex: smem exchange for k-groups 1..3: (NG_-1)*HC_*128 ull = 12KB
__device__ __forceinline__ void run_cell(const float* __restrict__ in,
                                         float* __restrict__ hst,
                                         const unsigned long long* __restrict__ Wd,
                                         const float* __restrict__ prm,
                                         float* sred, float* sfin,
                                         unsigned long long* pex) {
    const int tid = threadIdx.x;
    const int p   = tid & 127;   // batch pair -> rows 2p, 2p+1
    const int g   = tid >> 7;    // k-group

    unsigned long long acc[HC_];
    #pragma unroll
    for (int c = 0; c < HC_; c++) acc[c] = 0ull;

    const float* inp = in + (size_t)(g * KG_) * B_ + 2 * p;
    const unsigned long long* wb = Wd + g * KG_;

    #pragma unroll 1
    for (int kk = 0; kk < KG_; kk += 8) {
        unsigned long long a[8];
        #pragma unroll
        for (int j = 0; j < 8; j++) {
            float2 av = __ldcg((const float2*)(inp + (size_t)(kk + j) * B_));
            a[j] = pk2(av.x, av.y);
        }
        #pragma unroll
        for (int c = 0; c < HC_; c++) {
            const ulonglong2* wp = (const ulonglong2*)(wb + c * 512 + kk);
            #pragma unroll
            for (int j2 = 0; j2 < 4; j2++) {
                ulonglong2 w = wp[j2];
                fma2(acc[c], a[2 * j2 + 0], w.x);
                fma2(acc[c], a[2 * j2 + 1], w.y);
            }
        }
    }

    __syncthreads();                       // pex safe to overwrite
    if (g) {
        #pragma unroll
        for (int c = 0; c < HC_; c++) pex[((g - 1) * HC_ + c) * 128 + p] = acc[c];
    }
    __syncthreads();

    float zx[HC_], zy[HC_], v8[8];
    if (g == 0) {
        #pragma unroll
        for (int c = 0; c < HC_; c++) {
            float ax, ay;
            upk2(ax, ay, acc[c]);
            #pragma unroll
            for (int gg = 0; gg < NG_ - 1; gg++) {
                float bx, by;
                upk2(bx, by, pex[(gg * HC_ + c) * 128 + p]);
                ax += bx; ay += by;
            }
            float bb = prm[0 * HC_ + c];
            ax += bb; ay += bb;
            zx[c] = ax; zy[c] = ay;
            v8[2 * c] = ax + ay;
            v8[2 * c + 1] = ax * ax + ay * ay;
        }
    } else {
        #pragma unroll
        for (int q = 0; q < 8; q++) v8[q] = 0.f;
        #pragma unroll
        for (int c = 0; c < HC_; c++) { zx[c] = 0.f; zy[c] = 0.f; }
    }

    block_reduce8(v8, sred, sfin);         // sums over batch (group 0 only contributed)

    if (g == 0) {
        #pragma unroll
        for (int c = 0; c < HC_; c++) {
            float m   = sfin[2 * c] * (1.f / B_);
            float var = sfin[2 * c + 1] * (1.f / B_) - m * m;
            float rs  = rsqrtf(var + EPS_);
            float g1  = prm[2 * HC_ + c], be1 = prm[3 * HC_ + c], u = prm[1 * HC_ + c];
            float2 hv = __ldcg((const float2*)(hst + c * B_ + 2 * p));
            zx[c] = fmaxf(fmaf(hv.x, u, (zx[c] - m) * rs * g1 + be1), 0.f);
            zy[c] = fmaxf(fmaf(hv.y, u, (zy[c] - m) * rs * g1 + be1), 0.f);
            v8[2 * c]     = zx[c] + zy[c];
            v8[2 * c + 1] = zx[c] * zx[c] + zy[c] * zy[c];
        }
    } else {
        #pragma unroll
        for (int q = 0; q < 8; q++) v8[q] = 0.f;
    }

    block_reduce8(v8, sred, sfin);

    if (g == 0) {
        #pragma unroll
        for (int c = 0; c < HC_; c++) {
            float m   = sfin[2 * c] * (1.f / B_);
            float var = sfin[2 * c + 1] * (1.f / B_) - m * m;
            float rs  = rsqrtf(var + EPS_);
            float g2  = prm[4 * HC_ + c], be2 = prm[5 * HC_ + c];
            float2 o;
            o.x = (zx[c] - m) * rs * g2 + be2;
            o.y = (zy[c] - m) * rs * g2 + be2;
            __stcg((float2*)(hst + c * B_ + 2 * p), o);
        }
    }
}

// ---------------- transpose x: [B][T][D] -> [T][D][B] ----------------
__global__ void transpose_kernel(const float* __restrict__ x) {
    __shared__ float sm[32][33];
    int t  = blockIdx.x;
    int k0 = blockIdx.y * 32;
    int i0 = blockIdx.z * 32;
    int tx = threadIdx.x, ty = threadIdx.y;
    sm[ty][tx] = x[((size_t)(i0 + ty) * T_ + t) * D_ + (k0 + tx)];
    __syncthreads();
    d_xT[((size_t)t * D_ + (k0 + ty)) * B_ + (i0 + tx)] = sm[tx][ty];
}

// ---------------- persistent recurrent kernel ----------------
__global__ void __launch_bounds__(NT_, 1) rnn_kernel(
    const float* __restrict__ W0,  const float* __restrict__ b0,
    const float* __restrict__ u0,  const float* __restrict__ g10,
    const float* __restrict__ be10,const float* __restrict__ g20,
    const float* __restrict__ be20,
    const float* __restrict__ Wm,  const float* __restrict__ bm,
    const float* __restrict__ um,  const float* __restrict__ g1m,
    const float* __restrict__ be1m,const float* __restrict__ g2m,
    const float* __restrict__ be2m,
    const float* __restrict__ Wfc, const float* __restrict__ bfc,
    float* __restrict__ out) {

    __shared__ __align__(16) unsigned long long W0d[HC_ * 512];   // 16 KB
    __shared__ __align__(16) unsigned long long Wmd[HC_ * 512];   // 16 KB
    __shared__ __align__(16) unsigned long long pex[(NG_ - 1) * HC_ * 128]; // 12 KB
    __shared__ float p0[6 * HC_], pm[6 * HC_];
    __shared__ float sred[8 * NW_], sfin[8];

    const int tid   = threadIdx.x;
    const int jbase = blockIdx.x * HC_;

    // Stage duplicated weights + params
    for (int idx = tid; idx < HC_ * 512; idx += NT_) {
        int c = idx >> 9, k = idx & 511;
        float w0 = W0[(size_t)(jbase + c) * D_ + k];
        float wm = Wm[(size_t)(jbase + c) * H_ + k];
        W0d[idx] = pk2(w0, w0);
        Wmd[idx] = pk2(wm, wm);
    }
    if (tid < HC_) {
        int j = jbase + tid;
        p0[0 * HC_ + tid] = b0[j];  p0[1 * HC_ + tid] = u0[j];
        p0[2 * HC_ + tid] = g10[j]; p0[3 * HC_ + tid] = be10[j];
        p0[4 * HC_ + tid] = g20[j]; p0[5 * HC_ + tid] = be20[j];
        pm[0 * HC_ + tid] = bm[j];  pm[1 * HC_ + tid] = um[j];
        pm[2 * HC_ + tid] = g1m[j]; pm[3 * HC_ + tid] = be1m[j];
        pm[4 * HC_ + tid] = g2m[j]; pm[5 * HC_ + tid] = be2m[j];
    }
    // Zero state (per-launch; graph replays)
    if (tid < B_) {
        #pragma unroll
        for (int c = 0; c < HC_; c++) {
            __stcg(&d_h0 [(size_t)(jbase + c) * B_ + tid], 0.f);
            __stcg(&d_hm0[(size_t)(jbase + c) * B_ + tid], 0.f);
            __stcg(&d_hm1[(size_t)(jbase + c) * B_ + tid], 0.f);
        }
    }
    __syncthreads();
    gsync();

    // ---- sequential scan ----
    for (int t = 0; t < T_; t++) {
        run_cell(d_xT + (size_t)t * D_ * B_, d_h0 + (size_t)jbase * B_, W0d, p0,
                 sred, sfin, pex);
        gsync();
        run_cell(d_h0,  d_hm0 + (size_t)jbase * B_, Wmd, pm, sred, sfin, pex);
        gsync();
        run_cell(d_hm0, d_hm1 + (size_t)jbase * B_, Wmd, pm, sred, sfin, pex);
        // no sync needed: next L0 reads only xT + its own h0 cols;
        // hm0 is not rewritten until after the next gsync.
    }
    gsync();

    // ---- head: logits + log_softmax ----
    float* hrow = (float*)pex;   // reuse 12KB smem
    for (int rr = 0; rr < 2; rr++) {
        int r = blockIdx.x * 2 + rr;
        __syncthreads();
        for (int j = tid; j < H_; j += NT_) hrow[j] = __ldcg(&d_hm1[(size_t)j * B_ + r]);
        __syncthreads();

        float acc = -INFINITY;
        if (tid < O_) {
            acc = bfc[tid];
            const float4* wrow = (const float4*)(Wfc + (size_t)tid * H_);
            #pragma unroll 4
            for (int j4 = 0; j4 < H_ / 4; j4++) {
                float4 w = wrow[j4];
                acc = fmaf(hrow[4 * j4 + 0], w.x, acc);
                acc = fmaf(hrow[4 * j4 + 1], w.y, acc);
                acc = fmaf(hrow[4 * j4 + 2], w.z, acc);
                acc = fmaf(hrow[4 * j4 + 3], w.w, acc);
            }
        }
        float mx = block_allreduce_max(acc, sred);
        float e  = (tid < O_) ? expf(acc - mx) : 0.f;
        float se = block_allreduce_sum(e, sred);
        if (tid < O_) out[(size_t)r * O_ + tid] = acc - mx - logf(se);
    }
}

// ---------------- harness entry ----------------
extern "C" void kernel_launch(void* const* d_in, const int* in_sizes, int n_in,
                              void* d_out, int out_size) {
    (void)in_sizes; (void)n_in; (void)out_size;
    const float* x    = (const float*)d_in[0];
    const float* W0   = (const float*)d_in[1];
    const float* b0   = (const float*)d_in[2];
    const float* u0   = (const float*)d_in[3];
    const float* g10  = (const float*)d_in[4];
    const float* be10 = (const float*)d_in[5];
    const float* g20  = (const float*)d_in[6];
    const float* be20 = (const float*)d_in[7];
    const float* Wm   = (const float*)d_in[8];
    const float* bm   = (const float*)d_in[9];
    const float* um   = (const float*)d_in[10];
    const float* g1m  = (const float*)d_in[11];
    const float* be1m = (const float*)d_in[12];
    const float* g2m  = (const float*)d_in[13];
    const float* be2m = (const float*)d_in[14];
    const float* Wfc  = (const float*)d_in[15];
    const float* bfc  = (const float*)d_in[16];
    float* out = (float*)d_out;

    transpose_kernel<<<dim3(T_, D_ / 32, B_ / 32), dim3(32, 32)>>>(x);
    rnn_kernel<<<G_, NT_>>>(W0, b0, u0, g10, be10, g20, be20,
                            Wm, bm, um, g1m, be1m, g2m, be2m,
                            Wfc, bfc, out);
}

// round 3
// speedup vs baseline: 2.4557x; 1.5712x over previous
#include <cuda_runtime.h>
#include <math.h>

#define B_   256
#define T_   256
#define D_   512
#define H_   512
#define O_   256
#define EPS_ 1e-5f

#define G_   128   // persistent CTAs
#define HC_  4     // feature columns per CTA
#define NT_  512   // 128 batch-pairs x 4 k-groups
#define NG_  4     // k-groups
#define KG_  128   // k per group
#define NW_  (NT_/32)
#define NS_  (T_ + 2)   // wavefront steps

// ---------------- static device scratch ----------------
__device__ float d_xT[(size_t)T_ * D_ * B_];   // [t][k][i]
__device__ float d_h0 [2][H_ * B_];            // ping-pong
__device__ float d_hm0[2][H_ * B_];            // ping-pong
__device__ float d_hm1[H_ * B_];               // own-column only until head

__device__ unsigned          g_cnt;
__device__ volatile unsigned g_gen;

typedef unsigned long long ull;

// ---------------- packed f32x2 helpers ----------------
__device__ __forceinline__ ull pk2(float x, float y) {
    ull r; asm("mov.b64 %0, {%1, %2};" : "=l"(r) : "f"(x), "f"(y)); return r;
}
__device__ __forceinline__ void upk2(float& x, float& y, ull v) {
    asm("mov.b64 {%0, %1}, %2;" : "=f"(x), "=f"(y) : "l"(v));
}
__device__ __forceinline__ void fma2(ull& d, ull a, ull b) {
    asm("fma.rn.f32x2 %0, %1, %2, %0;" : "+l"(d) : "l"(a), "l"(b));
}
__device__ __forceinline__ ull ldcg64(const float* p) {
    return __ldcg((const ull*)p);
}

// ---------------- software grid barrier ----------------
__device__ __forceinline__ void gsync() {
    __syncthreads();
    if (threadIdx.x == 0) {
        __threadfence();
        unsigned my = g_gen;
        if (atomicAdd(&g_cnt, 1u) == (unsigned)(G_ - 1)) {
            g_cnt = 0u;
            __threadfence();
            g_gen = my + 1u;
        } else {
            while (g_gen == my) { __nanosleep(32); }
            __threadfence();
        }
    }
    __syncthreads();
}

// ---------------- slotted block reduction ----------------
// Each thread contributes 8 stats for its cell cl = tid>>7 (cl==3 is dummy).
// sred: [32 slots][4 warps-in-group]; sfin: [32].
__device__ __forceinline__ void block_reduce_cells(float v[8], float* sred, float* sfin) {
    const int tid = threadIdx.x;
    const int cl  = tid >> 7;
    const int wl  = (tid >> 5) & 3;
    __syncthreads();
    #pragma unroll
    for (int off = 16; off > 0; off >>= 1) {
        #pragma unroll
        for (int q = 0; q < 8; q++) v[q] += __shfl_down_sync(0xffffffffu, v[q], off);
    }
    if ((tid & 31) == 0) {
        #pragma unroll
        for (int q = 0; q < 8; q++) sred[(cl * 8 + q) * 4 + wl] = v[q];
    }
    __syncthreads();
    if (tid < 32) {
        sfin[tid] = sred[tid * 4 + 0] + sred[tid * 4 + 1] +
                    sred[tid * 4 + 2] + sred[tid * 4 + 3];
    }
    __syncthreads();
}

__device__ __forceinline__ float block_allreduce_max(float v, float* s) {
    __syncthreads();
    #pragma unroll
    for (int off = 16; off > 0; off >>= 1)
        v = fmaxf(v, __shfl_xor_sync(0xffffffffu, v, off));
    if ((threadIdx.x & 31) == 0) s[threadIdx.x >> 5] = v;
    __syncthreads();
    float m = s[0];
    #pragma unroll
    for (int w = 1; w < NW_; w++) m = fmaxf(m, s[w]);
    return m;
}
__device__ __forceinline__ float block_allreduce_sum(float v, float* s) {
    __syncthreads();
    #pragma unroll
    for (int off = 16; off > 0; off >>= 1)
        v += __shfl_xor_sync(0xffffffffu, v, off);
    if ((threadIdx.x & 31) == 0) s[threadIdx.x >> 5] = v;
    __syncthreads();
    float r = 0.f;
    #pragma unroll
    for (int w = 0; w < NW_; w++) r += s[w];
    return r;
}

// ---------------- transpose x: [B][T][D] -> [T][D][B] ----------------
__global__ void transpose_kernel(const float* __restrict__ x) {
    __shared__ float sm[32][33];
    int t  = blockIdx.x;
    int k0 = blockIdx.y * 32;
    int i0 = blockIdx.z * 32;
    int tx = threadIdx.x, ty = threadIdx.y;
    sm[ty][tx] = x[((size_t)(i0 + ty) * T_ + t) * D_ + (k0 + tx)];
    __syncthreads();
    d_xT[((size_t)t * D_ + (k0 + ty)) * B_ + (i0 + tx)] = sm[tx][ty];
}

// ---------------- persistent wavefront kernel ----------------
__global__ void __launch_bounds__(NT_, 1) rnn_kernel(
    const float* __restrict__ W0,  const float* __restrict__ b0,
    const float* __restrict__ u0,  const float* __restrict__ g10,
    const float* __restrict__ be10,const float* __restrict__ g20,
    const float* __restrict__ be20,
    const float* __restrict__ Wm,  const float* __restrict__ bm,
    const float* __restrict__ um,  const float* __restrict__ g1m,
    const float* __restrict__ be1m,const float* __restrict__ g2m,
    const float* __restrict__ be2m,
    const float* __restrict__ Wfc, const float* __restrict__ bfc,
    float* __restrict__ out) {

    __shared__ __align__(16) ull W0d[HC_ * 512];            // 16 KB (w,w) pairs
    __shared__ __align__(16) ull Wmd[HC_ * 512];            // 16 KB
    __shared__ __align__(16) ull pex[3 * HC_ * 128];        // 12 KB (3 writer groups)
    __shared__ float p0[6 * HC_], pm[6 * HC_];
    __shared__ float sred[32 * 4], sfin[32];

    const int tid   = threadIdx.x;
    const int p     = tid & 127;    // batch pair -> rows 2p, 2p+1
    const int g     = tid >> 7;     // k-group (and BN-cell owner if g<3)
    const int jbase = blockIdx.x * HC_;

    // Stage duplicated weights + params
    for (int idx = tid; idx < HC_ * 512; idx += NT_) {
        int c = idx >> 9, k = idx & 511;
        float w0 = W0[(size_t)(jbase + c) * D_ + k];
        float wm = Wm[(size_t)(jbase + c) * H_ + k];
        W0d[idx] = pk2(w0, w0);
        Wmd[idx] = pk2(wm, wm);
    }
    if (tid < HC_) {
        int j = jbase + tid;
        p0[0 * HC_ + tid] = b0[j];  p0[1 * HC_ + tid] = u0[j];
        p0[2 * HC_ + tid] = g10[j]; p0[3 * HC_ + tid] = be10[j];
        p0[4 * HC_ + tid] = g20[j]; p0[5 * HC_ + tid] = be20[j];
        pm[0 * HC_ + tid] = bm[j];  pm[1 * HC_ + tid] = um[j];
        pm[2 * HC_ + tid] = g1m[j]; pm[3 * HC_ + tid] = be1m[j];
        pm[4 * HC_ + tid] = g2m[j]; pm[5 * HC_ + tid] = be2m[j];
    }
    // Zero states (per-launch; graph replays)
    if (tid < B_) {
        #pragma unroll
        for (int c = 0; c < HC_; c++) {
            size_t o = (size_t)(jbase + c) * B_ + tid;
            __stcg(&d_h0 [0][o], 0.f); __stcg(&d_h0 [1][o], 0.f);
            __stcg(&d_hm0[0][o], 0.f); __stcg(&d_hm0[1][o], 0.f);
            __stcg(&d_hm1[o], 0.f);
        }
    }
    __syncthreads();
    gsync();

    // ---- wavefront: step s computes L0(t=s), L1(t=s-1), L2(t=s-2) ----
    for (int s = 0; s < NS_; s++) {
        const int rd = (s + 1) & 1;     // buffers written at step s-1
        const int wr = s & 1;
        const int tt = (s < T_) ? s : (T_ - 1);

        const float* in0 = d_xT + (size_t)tt * D_ * B_ + (size_t)(g * KG_) * B_ + 2 * p;
        const float* in1 = d_h0 [rd] + (size_t)(g * KG_) * B_ + 2 * p;
        const float* in2 = d_hm0[rd] + (size_t)(g * KG_) * B_ + 2 * p;

        ull acc0[HC_], acc1[HC_], acc2[HC_];
        #pragma unroll
        for (int c = 0; c < HC_; c++) { acc0[c] = 0; acc1[c] = 0; acc2[c] = 0; }

        const int kb = g * KG_;
        #pragma unroll 1
        for (int kk = 0; kk < KG_; kk += 8) {
            ull a0[8], a1[8], a2[8];
            #pragma unroll
            for (int j = 0; j < 8; j++) a0[j] = ldcg64(in0 + (size_t)(kk + j) * B_);
            #pragma unroll
            for (int j = 0; j < 8; j++) a1[j] = ldcg64(in1 + (size_t)(kk + j) * B_);
            // cell 0 (W0)
            #pragma unroll
            for (int c = 0; c < HC_; c++) {
                const ulonglong2* wp = (const ulonglong2*)(W0d + c * 512 + kb + kk);
                #pragma unroll
                for (int j2 = 0; j2 < 4; j2++) {
                    ulonglong2 w = wp[j2];
                    fma2(acc0[c], a0[2 * j2 + 0], w.x);
                    fma2(acc0[c], a0[2 * j2 + 1], w.y);
                }
            }
            #pragma unroll
            for (int j = 0; j < 8; j++) a2[j] = ldcg64(in2 + (size_t)(kk + j) * B_);
            // cells 1 & 2 share Wm loads
            #pragma unroll
            for (int c = 0; c < HC_; c++) {
                const ulonglong2* wp = (const ulonglong2*)(Wmd + c * 512 + kb + kk);
                #pragma unroll
                for (int j2 = 0; j2 < 4; j2++) {
                    ulonglong2 w = wp[j2];
                    fma2(acc1[c], a1[2 * j2 + 0], w.x);
                    fma2(acc1[c], a1[2 * j2 + 1], w.y);
                    fma2(acc2[c], a2[2 * j2 + 0], w.x);
                    fma2(acc2[c], a2[2 * j2 + 1], w.y);
                }
            }
        }

        // ---- k-partial exchange: 3 phases reusing one 12KB buffer ----
        float zx[HC_], zy[HC_], v8[8];
        #pragma unroll
        for (int q = 0; q < 8; q++) v8[q] = 0.f;

        #pragma unroll
        for (int cell = 0; cell < 3; cell++) {
            __syncthreads();
            if (g != cell) {
                int sg = g - (g > cell ? 1 : 0);
                #pragma unroll
                for (int c = 0; c < HC_; c++) {
                    ull pv = (cell == 0) ? acc0[c] : (cell == 1) ? acc1[c] : acc2[c];
                    pex[(sg * HC_ + c) * 128 + p] = pv;
                }
            }
            __syncthreads();
            if (g == cell) {
                const float* bia = (cell == 0) ? p0 : pm;
                #pragma unroll
                for (int c = 0; c < HC_; c++) {
                    float ax, ay;
                    ull mine = (cell == 0) ? acc0[c] : (cell == 1) ? acc1[c] : acc2[c];
                    upk2(ax, ay, mine);
                    #pragma unroll
                    for (int sg = 0; sg < 3; sg++) {
                        float bx, by;
                        upk2(bx, by, pex[(sg * HC_ + c) * 128 + p]);
                        ax += bx; ay += by;
                    }
                    float bb = bia[0 * HC_ + c];
                    ax += bb; ay += bb;
                    zx[c] = ax; zy[c] = ay;
                    v8[2 * c]     = ax + ay;
                    v8[2 * c + 1] = ax * ax + ay * ay;
                }
            }
        }

        // ---- BN1 stats (24 slots) ----
        block_reduce_cells(v8, sred, sfin);

        float* hst_old = (g == 0) ? (d_h0[rd] + (size_t)jbase * B_)
                       : (g == 1) ? (d_hm0[rd] + (size_t)jbase * B_)
                                  : (d_hm1 + (size_t)jbase * B_);
        float* hst_new = (g == 0) ? (d_h0[wr] + (size_t)jbase * B_)
                       : (g == 1) ? (d_hm0[wr] + (size_t)jbase * B_)
                                  : (d_hm1 + (size_t)jbase * B_);
        const float* prm = (g == 0) ? p0 : pm;

        if (g < 3) {
            #pragma unroll
            for (int c = 0; c < HC_; c++) {
                float m   = sfin[g * 8 + 2 * c] * (1.f / B_);
                float var = sfin[g * 8 + 2 * c + 1] * (1.f / B_) - m * m;
                float rs  = rsqrtf(var + EPS_);
                float g1  = prm[2 * HC_ + c], be1 = prm[3 * HC_ + c], u = prm[1 * HC_ + c];
                float2 hv = __ldcg((const float2*)(hst_old + c * B_ + 2 * p));
                zx[c] = fmaxf(fmaf(hv.x, u, (zx[c] - m) * rs * g1 + be1), 0.f);
                zy[c] = fmaxf(fmaf(hv.y, u, (zy[c] - m) * rs * g1 + be1), 0.f);
                v8[2 * c]     = zx[c] + zy[c];
                v8[2 * c + 1] = zx[c] * zx[c] + zy[c] * zy[c];
            }
        } else {
            #pragma unroll
            for (int q = 0; q < 8; q++) v8[q] = 0.f;
        }

        // ---- BN2 stats ----
        block_reduce_cells(v8, sred, sfin);

        const bool act = (g == 0) ? (s < T_)
                       : (g == 1) ? (s >= 1 && s <= T_)
                       : (g == 2) ? (s >= 2) : false;
        if (act) {
            #pragma unroll
            for (int c = 0; c < HC_; c++) {
                float m   = sfin[g * 8 + 2 * c] * (1.f / B_);
                float var = sfin[g * 8 + 2 * c + 1] * (1.f / B_) - m * m;
                float rs  = rsqrtf(var + EPS_);
                float g2  = prm[4 * HC_ + c], be2 = prm[5 * HC_ + c];
                float2 o;
                o.x = (zx[c] - m) * rs * g2 + be2;
                o.y = (zy[c] - m) * rs * g2 + be2;
                __stcg((float2*)(hst_new + c * B_ + 2 * p), o);
            }
        }

        gsync();   // publish this step's writes
    }

    // ---- head: logits + log_softmax (2 batch rows per CTA) ----
    float* hrow = (float*)pex;   // reuse smem
    for (int rr = 0; rr < 2; rr++) {
        int r = blockIdx.x * 2 + rr;
        __syncthreads();
        for (int j = tid; j < H_; j += NT_) hrow[j] = __ldcg(&d_hm1[(size_t)j * B_ + r]);
        __syncthreads();

        float acc = -INFINITY;
        if (tid < O_) {
            acc = bfc[tid];
            const float4* wrow = (const float4*)(Wfc + (size_t)tid * H_);
            #pragma unroll 4
            for (int j4 = 0; j4 < H_ / 4; j4++) {
                float4 w = wrow[j4];
                acc = fmaf(hrow[4 * j4 + 0], w.x, acc);
                acc = fmaf(hrow[4 * j4 + 1], w.y, acc);
                acc = fmaf(hrow[4 * j4 + 2], w.z, acc);
                acc = fmaf(hrow[4 * j4 + 3], w.w, acc);
            }
        }
        float mx = block_allreduce_max(acc, sred);
        float e  = (tid < O_) ? expf(acc - mx) : 0.f;
        float se = block_allreduce_sum(e, sred);
        if (tid < O_) out[(size_t)r * O_ + tid] = acc - mx - logf(se);
    }
}

// ---------------- harness entry ----------------
extern "C" void kernel_launch(void* const* d_in, const int* in_sizes, int n_in,
                              void* d_out, int out_size) {
    (void)in_sizes; (void)n_in; (void)out_size;
    const float* x    = (const float*)d_in[0];
    const float* W0   = (const float*)d_in[1];
    const float* b0   = (const float*)d_in[2];
    const float* u0   = (const float*)d_in[3];
    const float* g10  = (const float*)d_in[4];
    const float* be10 = (const float*)d_in[5];
    const float* g20  = (const float*)d_in[6];
    const float* be20 = (const float*)d_in[7];
    const float* Wm   = (const float*)d_in[8];
    const float* bm   = (const float*)d_in[9];
    const float* um   = (const float*)d_in[10];
    const float* g1m  = (const float*)d_in[11];
    const float* be1m = (const float*)d_in[12];
    const float* g2m  = (const float*)d_in[13];
    const float* be2m = (const float*)d_in[14];
    const float* Wfc  = (const float*)d_in[15];
    const float* bfc  = (const float*)d_in[16];
    float* out = (float*)d_out;

    transpose_kernel<<<dim3(T_, D_ / 32, B_ / 32), dim3(32, 32)>>>(x);
    rnn_kernel<<<G_, NT_>>>(W0, b0, u0, g10, be10, g20, be20,
                            Wm, bm, um, g1m, be1m, g2m, be2m,
                            Wfc, bfc, out);
}